// round 4
// baseline (speedup 1.0000x reference)
#include <cuda_runtime.h>
#include <stdint.h>

#define TT 3
#define FF 17
#define NN 8
#define DT 0.2f
#define EPS 1e-8f

// PWL representation of the three hot MLPs (an=0, rn=1, rb=2):
//   f(x) = A[k]*x + C[k],  k = #{ j : t_j <= x } over sorted thresholds t[0..31]
__device__ float g_t[3][32];
__device__ float g_A[3][33];
__device__ float g_C[3][33];
__device__ float g_attr_dl[8];

// ---------------------------------------------------------------------------
// Setup: build PWL tables (1 warp) + dl-MLP constants (dur depends only on
// ego[1], fixed batch row in the reference).
// ---------------------------------------------------------------------------
__global__ void sfm_precompute(const float* __restrict__ ego,
    const float* __restrict__ an_wi, const float* __restrict__ an_bi,
    const float* __restrict__ an_wo, const float* __restrict__ an_bo,
    const float* __restrict__ rn_wi, const float* __restrict__ rn_bi,
    const float* __restrict__ rn_wo, const float* __restrict__ rn_bo,
    const float* __restrict__ rb_wi, const float* __restrict__ rb_bi,
    const float* __restrict__ rb_wo, const float* __restrict__ rb_bo,
    const float* __restrict__ dl_wi, const float* __restrict__ dl_bi,
    const float* __restrict__ dl_wo, const float* __restrict__ dl_bo)
{
    __shared__ float sh_t[32], sh_s[32], sh_i[32];
    int lane = threadIdx.x;
    const float PINF = __int_as_float(0x7f800000);

    for (int m = 0; m < 3; m++) {
        const float* wi = (m == 0) ? an_wi : (m == 1) ? rn_wi : rb_wi;
        const float* bi = (m == 0) ? an_bi : (m == 1) ? rn_bi : rb_bi;
        const float* wo = (m == 0) ? an_wo : (m == 1) ? rn_wo : rb_wo;
        const float* bo = (m == 0) ? an_bo : (m == 1) ? rn_bo : rb_bo;

        float wiv = wi[lane], biv = bi[lane], wov = wo[lane];
        // relu(-(wi*x+bi)) active iff x < t  (wi uniform >= 0)
        float t, slope, icept;
        if (wiv > 0.f) {
            t = -biv / wiv;
            slope = -wov * wiv;
            icept = -wov * biv;
        } else if (biv < 0.f) {       // always active, constant -bi
            t = PINF; slope = 0.f; icept = -wov * biv;
        } else {                      // never active
            t = -PINF; slope = 0.f; icept = 0.f;
        }

        // rank-sort ascending (ties by lane) via shuffles
        int rank = 0;
        for (int i = 0; i < 32; i++) {
            float ti = __shfl_sync(0xffffffffu, t, i);
            rank += (ti < t) || (ti == t && i < lane);
        }
        sh_t[rank] = t; sh_s[rank] = slope; sh_i[rank] = icept;
        __syncwarp();
        g_t[m][lane] = sh_t[lane];
        if (lane == 0) {
            double A = 0.0, C = (double)bo[0];
            g_A[m][32] = 0.f; g_C[m][32] = (float)C;
            for (int k = 31; k >= 0; k--) {
                A += (double)sh_s[k];
                C += (double)sh_i[k];
                g_A[m][k] = (float)A;
                g_C[m][k] = (float)C;
            }
        }
        __syncwarp();
    }

    // dl MLP on dur[n] (depends only on ego batch row 1)
    if (lane < 8) {
        const float* e1 = ego + (size_t)1 * TT * FF;
        float id = e1[(TT - 1) * FF + 8 + lane];
        float dur = 0.f;
#pragma unroll
        for (int t = 0; t < TT; t++) {
            bool found = false;
#pragma unroll
            for (int k = 0; k < 8; k++)
                found = found || (e1[t * FF + 8 + k] == id);
            dur += found ? 1.f : 0.f;
        }
        float acc = dl_bo[0];
#pragma unroll
        for (int j = 0; j < 32; j++) {
            float h = fmaxf(-fmaf(dl_wi[j], dur, dl_bi[j]), 0.f);
            acc = fmaf(dl_wo[j], h, acc);
        }
        g_attr_dl[lane] = acc;
    }
}

// Branchless count of sorted thresholds <= x (k in [0,32]), then 1 FMA.
__device__ __forceinline__ float pwl_eval(const float* __restrict__ t,
                                          const float* __restrict__ A,
                                          const float* __restrict__ C,
                                          float x)
{
    int k = 0;
    if (t[15]    <= x) k  = 16;
    if (t[k + 7] <= x) k += 8;
    if (t[k + 3] <= x) k += 4;
    if (t[k + 1] <= x) k += 2;
    if (t[k]     <= x) k += 1;   // k in [0,31]
    if (t[31]    <= x) k += 1;   // all <= x  => k = 32
    return fmaf(A[k], x, C[k]);
}

// ---------------------------------------------------------------------------
// Main kernel: one thread per agent. ALL global accesses are scalar floats —
// no vector loads anywhere (two rounds of misaligned-address failures).
// ---------------------------------------------------------------------------
__global__ void __launch_bounds__(256, 5) sfm_main(
    const float* __restrict__ ego, const float* __restrict__ nei,
    const float* __restrict__ border, const float* __restrict__ adp,
    const float* __restrict__ eff_angle,
    float* __restrict__ out, int n_batch)
{
    __shared__ float st[3][32];
    __shared__ float sA[3][33];
    __shared__ float sC[3][33];
    __shared__ float sdl[8];

    int tid = threadIdx.x;
    for (int i = tid; i < 96; i += 256) ((float*)st)[i] = ((const float*)g_t)[i];
    for (int i = tid; i < 99; i += 256) ((float*)sA)[i] = ((const float*)g_A)[i];
    for (int i = tid; i < 99; i += 256) ((float*)sC)[i] = ((const float*)g_C)[i];
    if (tid < 8) sdl[tid] = g_attr_dl[tid];
    __syncthreads();

    int b = blockIdx.x * 256 + tid;
    if (b >= n_batch) return;

    // ego_last fields 0..5 (scalar loads)
    const float* eg = ego + (size_t)b * (TT * FF) + (TT - 1) * FF;
    float g0 = eg[0], g1 = eg[1], g2 = eg[2], g3 = eg[3], g4 = eg[4], g5 = eg[5];

    // heading + angle threshold (division-free clamp: |dot| > thr * ||f||)
    float einv = rsqrtf(g4 * g4 + g5 * g5);
    float ex = g4 * einv, ey = g5 * einv;
    float na = fmaxf(sqrtf(ex * ex + ey * ey), EPS);
    float thr = eff_angle[0] * na;

    float ax = 0.f, ay = 0.f;

    // f_dest: v34 = (g3, g4); dv = (|v34|, 0)
    {
        float nv = sqrtf(g3 * g3 + g4 * g4);
        float p0 = adp[0], p1 = adp[1];
        float fx = (p1 * nv - g3) / p0;
        float fy = (0.f - g4) / p0;
        float dot = ex * fx + ey * fy;
        float nbn = fmaxf(sqrtf(fx * fx + fy * fy), EPS);
        bool keep = fabsf(dot) > thr * nbn;
        ax += keep ? fx : 0.f;
        ay += keep ? fy : 0.f;
    }

    // neighbors: attr + repu share direction r, so one keep-test covers both
    const float* nb = nei + (size_t)b * (NN * FF);
#pragma unroll
    for (int n = 0; n < 8; n++) {
        const float* p = nb + n * FF;
        float a2 = p[2], a3 = p[3], a4 = p[4], a5 = p[5];

        bool mx = (a2 == 0.f), my = (a3 == 0.f);
        float rx = a2 - g2, ry = a3 - g3;
        float rnm = sqrtf(rx * rx + ry * ry);
        float vx = a4 * DT, vy = a5 * DT;
        float px = rx + vx, py = ry + vy;
        float bbv = sqrtf(rnm + px * px + py * py - vx * vx - vy * vy) * 0.5f;

        float fa = pwl_eval(st[0], sA[0], sC[0], rnm);   // an MLP on r_norm
        float fr = pwl_eval(st[1], sA[1], sC[1], bbv);   // rn MLP on b
        float s = (fa * sdl[n] + fr) / rnm;              // combined scalar factor

        float fxb = mx ? 0.f : rx;
        float fyb = my ? 0.f : ry;
        float dot = ex * fxb + ey * fyb;
        float nbn = sqrtf(fxb * fxb + fyb * fyb);
        bool keep = fabsf(dot) > thr * nbn;
        ax += keep ? s * fxb : 0.f;
        ay += keep ? s * fyb : 0.f;
    }

    // f_bor: y-only vectors, magnitude rb(|rbv|), direction sign(rbv)
    {
        float rbv0 = g3 - border[0];
        float rbv1 = g3 - border[3];
        float rbn0 = fabsf(rbv0), rbn1 = fabsf(rbv1);

        float m0 = pwl_eval(st[2], sA[2], sC[2], rbn0);
        float m1 = pwl_eval(st[2], sA[2], sC[2], rbn1);

        float fy0 = m0 * (rbv0 / rbn0);
        float nbn0 = fmaxf(fabsf(fy0), EPS);
        if (fabsf(ey * fy0) > thr * nbn0) ay += fy0;

        float fy1 = m1 * (rbv1 / rbn1);
        float nbn1 = fmaxf(fabsf(fy1), EPS);
        if (fabsf(ey * fy1) > thr * nbn1) ay += fy1;
    }

    float vxo = g2 + ax * DT;
    float vyo = g3 + ay * DT;
    float sx = g0 + vxo * DT;
    float sy = g1 + vyo * DT;

    float* o = out + (size_t)b * 6;     // scalar stores only
    o[0] = sx; o[1] = sy;
    o[2] = vxo; o[3] = vyo;
    o[4] = ax;  o[5] = ay;
}

extern "C" void kernel_launch(void* const* d_in, const int* in_sizes, int n_in,
                              void* d_out, int out_size)
{
    const float* ego    = (const float*)d_in[0];
    const float* nei    = (const float*)d_in[1];
    const float* border = (const float*)d_in[2];
    const float* adp    = (const float*)d_in[3];
    const float* eff    = (const float*)d_in[4];
    const float* an_wi  = (const float*)d_in[5];
    const float* an_bi  = (const float*)d_in[6];
    const float* an_wo  = (const float*)d_in[7];
    const float* an_bo  = (const float*)d_in[8];
    const float* rn_wi  = (const float*)d_in[9];
    const float* rn_bi  = (const float*)d_in[10];
    const float* rn_wo  = (const float*)d_in[11];
    const float* rn_bo  = (const float*)d_in[12];
    const float* rb_wi  = (const float*)d_in[13];
    const float* rb_bi  = (const float*)d_in[14];
    const float* rb_wo  = (const float*)d_in[15];
    const float* rb_bo  = (const float*)d_in[16];
    const float* dl_wi  = (const float*)d_in[17];
    const float* dl_bi  = (const float*)d_in[18];
    const float* dl_wo  = (const float*)d_in[19];
    const float* dl_bo  = (const float*)d_in[20];
    float* out = (float*)d_out;

    int n_batch = in_sizes[0] / (TT * FF);

    sfm_precompute<<<1, 32>>>(ego,
                              an_wi, an_bi, an_wo, an_bo,
                              rn_wi, rn_bi, rn_wo, rn_bo,
                              rb_wi, rb_bi, rb_wo, rb_bo,
                              dl_wi, dl_bi, dl_wo, dl_bo);

    int blocks = (n_batch + 255) / 256;
    sfm_main<<<blocks, 256>>>(ego, nei, border, adp, eff, out, n_batch);
}

// round 5
// speedup vs baseline: 1.5096x; 1.5096x over previous
#include <cuda_runtime.h>
#include <stdint.h>

#define TT 3
#define FF 17
#define NN 8
#define DT 0.2f
#define EPS 1e-8f

// PWL representation of the three hot MLPs (an=0, rn=1, rb=2):
//   f(x) = A[k]*x + C[k],  k = #{ j : t_j <= x } over sorted thresholds t[0..31]
__device__ float g_t[3][32];
__device__ float g_A[3][33];
__device__ float g_C[3][33];
__device__ float g_attr_dl[8];

// ---------------------------------------------------------------------------
// Setup: 128 threads. Warps 0-2 build the three PWL tables IN PARALLEL using
// warp-parallel suffix scans (no serial double loops). Warp 3 (lanes 0-7)
// computes the dl-MLP constants (dur depends only on ego batch row 1).
// ---------------------------------------------------------------------------
__global__ void sfm_precompute(const float* __restrict__ ego,
    const float* __restrict__ an_wi, const float* __restrict__ an_bi,
    const float* __restrict__ an_wo, const float* __restrict__ an_bo,
    const float* __restrict__ rn_wi, const float* __restrict__ rn_bi,
    const float* __restrict__ rn_wo, const float* __restrict__ rn_bo,
    const float* __restrict__ rb_wi, const float* __restrict__ rb_bi,
    const float* __restrict__ rb_wo, const float* __restrict__ rb_bo,
    const float* __restrict__ dl_wi, const float* __restrict__ dl_bi,
    const float* __restrict__ dl_wo, const float* __restrict__ dl_bo)
{
    __shared__ float sh[3][3][32];
    int tid = threadIdx.x;
    int w = tid >> 5, lane = tid & 31;
    const unsigned FULL = 0xffffffffu;
    const float PINF = __int_as_float(0x7f800000);

    if (w < 3) {
        const float* wi = (w == 0) ? an_wi : (w == 1) ? rn_wi : rb_wi;
        const float* bi = (w == 0) ? an_bi : (w == 1) ? rn_bi : rb_bi;
        const float* wo = (w == 0) ? an_wo : (w == 1) ? rn_wo : rb_wo;
        const float* bo = (w == 0) ? an_bo : (w == 1) ? rn_bo : rb_bo;

        float wiv = wi[lane], biv = bi[lane], wov = wo[lane];
        float bov = bo[0];
        // relu(-(wi*x+bi)) active iff x < t  (wi uniform >= 0)
        float t, slope, icept;
        if (wiv > 0.f) {
            t = -biv / wiv;
            slope = -wov * wiv;
            icept = -wov * biv;
        } else if (biv < 0.f) {       // always active, constant -bi
            t = PINF; slope = 0.f; icept = -wov * biv;
        } else {                      // never active
            t = -PINF; slope = 0.f; icept = 0.f;
        }

        // rank-sort ascending (ties by lane) via shuffles
        int rank = 0;
#pragma unroll
        for (int i = 0; i < 32; i++) {
            float ti = __shfl_sync(FULL, t, i);
            rank += (ti < t) || (ti == t && i < lane);
        }
        sh[w][0][rank] = t; sh[w][1][rank] = slope; sh[w][2][rank] = icept;
        __syncwarp();
        float ts = sh[w][0][lane];
        float A  = sh[w][1][lane];
        float C  = sh[w][2][lane];

        // inclusive suffix scan: A[k] = sum_{j>=k} slope[j], same for C
#pragma unroll
        for (int off = 1; off < 32; off <<= 1) {
            float a2 = __shfl_down_sync(FULL, A, off);
            float c2 = __shfl_down_sync(FULL, C, off);
            if (lane + off < 32) { A += a2; C += c2; }
        }
        C += bov;

        g_t[w][lane] = ts;
        g_A[w][lane] = A;
        g_C[w][lane] = C;
        if (lane == 0) { g_A[w][32] = 0.f; g_C[w][32] = bov; }
    } else if (lane < 8) {
        // dl MLP on dur[n] (depends only on ego batch row 1)
        const float* e1 = ego + (size_t)1 * TT * FF;
        float id = e1[(TT - 1) * FF + 8 + lane];
        float dur = 0.f;
#pragma unroll
        for (int t = 0; t < TT; t++) {
            bool found = false;
#pragma unroll
            for (int k = 0; k < 8; k++)
                found = found || (e1[t * FF + 8 + k] == id);
            dur += found ? 1.f : 0.f;
        }
        float acc = dl_bo[0];
#pragma unroll
        for (int j = 0; j < 32; j++) {
            float h = fmaxf(-fmaf(dl_wi[j], dur, dl_bi[j]), 0.f);
            acc = fmaf(dl_wo[j], h, acc);
        }
        g_attr_dl[lane] = acc;
    }
}

// Branchless count of sorted thresholds <= x (k in [0,32]), then 1 FMA.
__device__ __forceinline__ float pwl_eval(const float* __restrict__ t,
                                          const float* __restrict__ A,
                                          const float* __restrict__ C,
                                          float x)
{
    int k = 0;
    if (t[15]    <= x) k  = 16;
    if (t[k + 7] <= x) k += 8;
    if (t[k + 3] <= x) k += 4;
    if (t[k + 1] <= x) k += 2;
    if (t[k]     <= x) k += 1;   // k in [0,31]
    if (t[31]    <= x) k += 1;   // all <= x  => k = 32
    return fmaf(A[k], x, C[k]);
}

// ---------------------------------------------------------------------------
// Main kernel: one thread per agent. ALL global accesses are scalar floats —
// no vector loads anywhere (misaligned-address failures in rounds 2-3).
// ---------------------------------------------------------------------------
__global__ void __launch_bounds__(256, 6) sfm_main(
    const float* __restrict__ ego, const float* __restrict__ nei,
    const float* __restrict__ border, const float* __restrict__ adp,
    const float* __restrict__ eff_angle,
    float* __restrict__ out, int n_batch)
{
    __shared__ float st[3][32];
    __shared__ float sA[3][33];
    __shared__ float sC[3][33];
    __shared__ float sdl[8];

    int tid = threadIdx.x;
    for (int i = tid; i < 96; i += 256) ((float*)st)[i] = ((const float*)g_t)[i];
    for (int i = tid; i < 99; i += 256) ((float*)sA)[i] = ((const float*)g_A)[i];
    for (int i = tid; i < 99; i += 256) ((float*)sC)[i] = ((const float*)g_C)[i];
    if (tid < 8) sdl[tid] = g_attr_dl[tid];
    __syncthreads();

    int b = blockIdx.x * 256 + tid;
    if (b >= n_batch) return;

    // ego_last fields 0..5 (scalar loads)
    const float* eg = ego + (size_t)b * (TT * FF) + (TT - 1) * FF;
    float g0 = eg[0], g1 = eg[1], g2 = eg[2], g3 = eg[3], g4 = eg[4], g5 = eg[5];

    // heading + angle threshold (division-free clamp: |dot| > thr * ||f||)
    float einv = rsqrtf(g4 * g4 + g5 * g5);
    float ex = g4 * einv, ey = g5 * einv;
    float na = fmaxf(sqrtf(ex * ex + ey * ey), EPS);
    float thr = eff_angle[0] * na;

    float ax = 0.f, ay = 0.f;

    // f_dest: v34 = (g3, g4); dv = (|v34|, 0)
    {
        float nv = sqrtf(g3 * g3 + g4 * g4);
        float p0 = adp[0], p1 = adp[1];
        float fx = (p1 * nv - g3) / p0;
        float fy = (0.f - g4) / p0;
        float dot = ex * fx + ey * fy;
        float nbn = fmaxf(sqrtf(fx * fx + fy * fy), EPS);
        bool keep = fabsf(dot) > thr * nbn;
        ax += keep ? fx : 0.f;
        ay += keep ? fy : 0.f;
    }

    // neighbors: attr + repu share direction r, so one keep-test covers both
    const float* nb = nei + (size_t)b * (NN * FF);
#pragma unroll
    for (int n = 0; n < 8; n++) {
        const float* p = nb + n * FF;
        float a2 = p[2], a3 = p[3], a4 = p[4], a5 = p[5];

        bool mx = (a2 == 0.f), my = (a3 == 0.f);
        float rx = a2 - g2, ry = a3 - g3;
        float rnm = sqrtf(rx * rx + ry * ry);
        float vx = a4 * DT, vy = a5 * DT;
        float px = rx + vx, py = ry + vy;
        float bbv = sqrtf(rnm + px * px + py * py - vx * vx - vy * vy) * 0.5f;

        float fa = pwl_eval(st[0], sA[0], sC[0], rnm);   // an MLP on r_norm
        float fr = pwl_eval(st[1], sA[1], sC[1], bbv);   // rn MLP on b
        float s = (fa * sdl[n] + fr) / rnm;              // combined scalar factor

        float fxb = mx ? 0.f : rx;
        float fyb = my ? 0.f : ry;
        float dot = ex * fxb + ey * fyb;
        float nbn = sqrtf(fxb * fxb + fyb * fyb);
        bool keep = fabsf(dot) > thr * nbn;
        ax += keep ? s * fxb : 0.f;
        ay += keep ? s * fyb : 0.f;
    }

    // f_bor: y-only vectors, magnitude rb(|rbv|), direction sign(rbv)
    {
        float rbv0 = g3 - border[0];
        float rbv1 = g3 - border[3];
        float rbn0 = fabsf(rbv0), rbn1 = fabsf(rbv1);

        float m0 = pwl_eval(st[2], sA[2], sC[2], rbn0);
        float m1 = pwl_eval(st[2], sA[2], sC[2], rbn1);

        float fy0 = m0 * (rbv0 / rbn0);
        float nbn0 = fmaxf(fabsf(fy0), EPS);
        if (fabsf(ey * fy0) > thr * nbn0) ay += fy0;

        float fy1 = m1 * (rbv1 / rbn1);
        float nbn1 = fmaxf(fabsf(fy1), EPS);
        if (fabsf(ey * fy1) > thr * nbn1) ay += fy1;
    }

    float vxo = g2 + ax * DT;
    float vyo = g3 + ay * DT;
    float sx = g0 + vxo * DT;
    float sy = g1 + vyo * DT;

    float* o = out + (size_t)b * 6;     // scalar stores only
    o[0] = sx; o[1] = sy;
    o[2] = vxo; o[3] = vyo;
    o[4] = ax;  o[5] = ay;
}

extern "C" void kernel_launch(void* const* d_in, const int* in_sizes, int n_in,
                              void* d_out, int out_size)
{
    const float* ego    = (const float*)d_in[0];
    const float* nei    = (const float*)d_in[1];
    const float* border = (const float*)d_in[2];
    const float* adp    = (const float*)d_in[3];
    const float* eff    = (const float*)d_in[4];
    const float* an_wi  = (const float*)d_in[5];
    const float* an_bi  = (const float*)d_in[6];
    const float* an_wo  = (const float*)d_in[7];
    const float* an_bo  = (const float*)d_in[8];
    const float* rn_wi  = (const float*)d_in[9];
    const float* rn_bi  = (const float*)d_in[10];
    const float* rn_wo  = (const float*)d_in[11];
    const float* rn_bo  = (const float*)d_in[12];
    const float* rb_wi  = (const float*)d_in[13];
    const float* rb_bi  = (const float*)d_in[14];
    const float* rb_wo  = (const float*)d_in[15];
    const float* rb_bo  = (const float*)d_in[16];
    const float* dl_wi  = (const float*)d_in[17];
    const float* dl_bi  = (const float*)d_in[18];
    const float* dl_wo  = (const float*)d_in[19];
    const float* dl_bo  = (const float*)d_in[20];
    float* out = (float*)d_out;

    int n_batch = in_sizes[0] / (TT * FF);

    sfm_precompute<<<1, 128>>>(ego,
                               an_wi, an_bi, an_wo, an_bo,
                               rn_wi, rn_bi, rn_wo, rn_bo,
                               rb_wi, rb_bi, rb_wo, rb_bo,
                               dl_wi, dl_bi, dl_wo, dl_bo);

    int blocks = (n_batch + 255) / 256;
    sfm_main<<<blocks, 256>>>(ego, nei, border, adp, eff, out, n_batch);
}

// round 6
// speedup vs baseline: 1.5447x; 1.0232x over previous
#include <cuda_runtime.h>
#include <stdint.h>

#define TT 3
#define FF 17
#define NN 8
#define DT 0.2f
#define EPS 1e-8f

// PWL representation of the three hot MLPs (an=0, rn=1, rb=2):
//   f(x) = A[k]*x + C[k],  k = #{ j : t_j <= x } over sorted thresholds t[0..31]
__device__ float g_t[3][32];
__device__ float g_A[3][33];
__device__ float g_C[3][33];
__device__ float g_attr_dl[8];

// ---------------------------------------------------------------------------
// Setup: 128 threads. Warps 0-2 build the three PWL tables IN PARALLEL using
// warp-parallel suffix scans. Warp 3 (lanes 0-7) computes the dl-MLP constants
// (dur depends only on ego batch row 1).
// ---------------------------------------------------------------------------
__global__ void sfm_precompute(const float* __restrict__ ego,
    const float* __restrict__ an_wi, const float* __restrict__ an_bi,
    const float* __restrict__ an_wo, const float* __restrict__ an_bo,
    const float* __restrict__ rn_wi, const float* __restrict__ rn_bi,
    const float* __restrict__ rn_wo, const float* __restrict__ rn_bo,
    const float* __restrict__ rb_wi, const float* __restrict__ rb_bi,
    const float* __restrict__ rb_wo, const float* __restrict__ rb_bo,
    const float* __restrict__ dl_wi, const float* __restrict__ dl_bi,
    const float* __restrict__ dl_wo, const float* __restrict__ dl_bo)
{
    __shared__ float sh[3][3][32];
    int tid = threadIdx.x;
    int w = tid >> 5, lane = tid & 31;
    const unsigned FULL = 0xffffffffu;
    const float PINF = __int_as_float(0x7f800000);

    if (w < 3) {
        const float* wi = (w == 0) ? an_wi : (w == 1) ? rn_wi : rb_wi;
        const float* bi = (w == 0) ? an_bi : (w == 1) ? rn_bi : rb_bi;
        const float* wo = (w == 0) ? an_wo : (w == 1) ? rn_wo : rb_wo;
        const float* bo = (w == 0) ? an_bo : (w == 1) ? rn_bo : rb_bo;

        float wiv = wi[lane], biv = bi[lane], wov = wo[lane];
        float bov = bo[0];
        // relu(-(wi*x+bi)) active iff x < t  (wi uniform >= 0)
        float t, slope, icept;
        if (wiv > 0.f) {
            t = -biv / wiv;
            slope = -wov * wiv;
            icept = -wov * biv;
        } else if (biv < 0.f) {       // always active, constant -bi
            t = PINF; slope = 0.f; icept = -wov * biv;
        } else {                      // never active
            t = -PINF; slope = 0.f; icept = 0.f;
        }

        // rank-sort ascending (ties by lane) via shuffles
        int rank = 0;
#pragma unroll
        for (int i = 0; i < 32; i++) {
            float ti = __shfl_sync(FULL, t, i);
            rank += (ti < t) || (ti == t && i < lane);
        }
        sh[w][0][rank] = t; sh[w][1][rank] = slope; sh[w][2][rank] = icept;
        __syncwarp();
        float ts = sh[w][0][lane];
        float A  = sh[w][1][lane];
        float C  = sh[w][2][lane];

        // inclusive suffix scan: A[k] = sum_{j>=k} slope[j], same for C
#pragma unroll
        for (int off = 1; off < 32; off <<= 1) {
            float a2 = __shfl_down_sync(FULL, A, off);
            float c2 = __shfl_down_sync(FULL, C, off);
            if (lane + off < 32) { A += a2; C += c2; }
        }
        C += bov;

        g_t[w][lane] = ts;
        g_A[w][lane] = A;
        g_C[w][lane] = C;
        if (lane == 0) { g_A[w][32] = 0.f; g_C[w][32] = bov; }
    } else if (lane < 8) {
        // dl MLP on dur[n] (depends only on ego batch row 1)
        const float* e1 = ego + (size_t)1 * TT * FF;
        float id = e1[(TT - 1) * FF + 8 + lane];
        float dur = 0.f;
#pragma unroll
        for (int t = 0; t < TT; t++) {
            bool found = false;
#pragma unroll
            for (int k = 0; k < 8; k++)
                found = found || (e1[t * FF + 8 + k] == id);
            dur += found ? 1.f : 0.f;
        }
        float acc = dl_bo[0];
#pragma unroll
        for (int j = 0; j < 32; j++) {
            float h = fmaxf(-fmaf(dl_wi[j], dur, dl_bi[j]), 0.f);
            acc = fmaf(dl_wo[j], h, acc);
        }
        g_attr_dl[lane] = acc;
    }
}

// Branchless count of sorted thresholds <= x (k in [0,32]), then 1 FMA.
__device__ __forceinline__ float pwl_eval(const float* __restrict__ t,
                                          const float* __restrict__ A,
                                          const float* __restrict__ C,
                                          float x)
{
    int k = 0;
    if (t[15]    <= x) k  = 16;
    if (t[k + 7] <= x) k += 8;
    if (t[k + 3] <= x) k += 4;
    if (t[k + 1] <= x) k += 2;
    if (t[k]     <= x) k += 1;   // k in [0,31]
    if (t[31]    <= x) k += 1;   // all <= x  => k = 32
    return fmaf(A[k], x, C[k]);
}

// ---------------------------------------------------------------------------
// Main kernel: one thread per agent. ALL global accesses are scalar floats
// (misaligned-address failures in rounds 2-3 with vector loads).
// ALL 38 loads are issued in one front batch (MLP ~38) before any compute.
// ---------------------------------------------------------------------------
__global__ void __launch_bounds__(256, 4) sfm_main(
    const float* __restrict__ ego, const float* __restrict__ nei,
    const float* __restrict__ border, const float* __restrict__ adp,
    const float* __restrict__ eff_angle,
    float* __restrict__ out, int n_batch)
{
    __shared__ float st[3][32];
    __shared__ float sA[3][33];
    __shared__ float sC[3][33];
    __shared__ float sdl[8];

    int tid = threadIdx.x;
    for (int i = tid; i < 96; i += 256) ((float*)st)[i] = ((const float*)g_t)[i];
    for (int i = tid; i < 99; i += 256) ((float*)sA)[i] = ((const float*)g_A)[i];
    for (int i = tid; i < 99; i += 256) ((float*)sC)[i] = ((const float*)g_C)[i];
    if (tid < 8) sdl[tid] = g_attr_dl[tid];
    __syncthreads();

    int b = blockIdx.x * 256 + tid;
    if (b >= n_batch) return;

    // ---- FRONT-BATCHED LOADS: issue everything before consuming anything ----
    const float* eg = ego + (size_t)b * (TT * FF) + (TT - 1) * FF;
    const float* nb = nei + (size_t)b * (NN * FF);

    float g0 = eg[0], g1 = eg[1], g2 = eg[2], g3 = eg[3], g4 = eg[4], g5 = eg[5];

    float a2[8], a3[8], a4[8], a5[8];
#pragma unroll
    for (int n = 0; n < 8; n++) {
        const float* p = nb + n * FF;
        a2[n] = p[2]; a3[n] = p[3]; a4[n] = p[4]; a5[n] = p[5];
    }

    // ---- compute phase ----
    // heading + angle threshold (division-free clamp: |dot| > thr * ||f||)
    float einv = rsqrtf(g4 * g4 + g5 * g5);
    float ex = g4 * einv, ey = g5 * einv;
    float na = fmaxf(sqrtf(ex * ex + ey * ey), EPS);
    float thr = eff_angle[0] * na;

    float ax = 0.f, ay = 0.f;

    // f_dest: v34 = (g3, g4); dv = (|v34|, 0)
    {
        float nv = sqrtf(g3 * g3 + g4 * g4);
        float p0 = adp[0], p1 = adp[1];
        float fx = (p1 * nv - g3) / p0;
        float fy = (0.f - g4) / p0;
        float dot = ex * fx + ey * fy;
        float nbn = fmaxf(sqrtf(fx * fx + fy * fy), EPS);
        bool keep = fabsf(dot) > thr * nbn;
        ax += keep ? fx : 0.f;
        ay += keep ? fy : 0.f;
    }

    // neighbors: attr + repu share direction r, so one keep-test covers both
#pragma unroll
    for (int n = 0; n < 8; n++) {
        bool mx = (a2[n] == 0.f), my = (a3[n] == 0.f);
        float rx = a2[n] - g2, ry = a3[n] - g3;
        float rnm = sqrtf(rx * rx + ry * ry);
        float vx = a4[n] * DT, vy = a5[n] * DT;
        float px = rx + vx, py = ry + vy;
        float bbv = sqrtf(rnm + px * px + py * py - vx * vx - vy * vy) * 0.5f;

        float fa = pwl_eval(st[0], sA[0], sC[0], rnm);   // an MLP on r_norm
        float fr = pwl_eval(st[1], sA[1], sC[1], bbv);   // rn MLP on b
        float s = (fa * sdl[n] + fr) / rnm;              // combined scalar factor

        float fxb = mx ? 0.f : rx;
        float fyb = my ? 0.f : ry;
        float dot = ex * fxb + ey * fyb;
        float nbn = sqrtf(fxb * fxb + fyb * fyb);
        bool keep = fabsf(dot) > thr * nbn;
        ax += keep ? s * fxb : 0.f;
        ay += keep ? s * fyb : 0.f;
    }

    // f_bor: y-only vectors, magnitude rb(|rbv|), direction sign(rbv)
    {
        float rbv0 = g3 - border[0];
        float rbv1 = g3 - border[3];
        float rbn0 = fabsf(rbv0), rbn1 = fabsf(rbv1);

        float m0 = pwl_eval(st[2], sA[2], sC[2], rbn0);
        float m1 = pwl_eval(st[2], sA[2], sC[2], rbn1);

        float fy0 = m0 * (rbv0 / rbn0);
        float nbn0 = fmaxf(fabsf(fy0), EPS);
        if (fabsf(ey * fy0) > thr * nbn0) ay += fy0;

        float fy1 = m1 * (rbv1 / rbn1);
        float nbn1 = fmaxf(fabsf(fy1), EPS);
        if (fabsf(ey * fy1) > thr * nbn1) ay += fy1;
    }

    float vxo = g2 + ax * DT;
    float vyo = g3 + ay * DT;
    float sx = g0 + vxo * DT;
    float sy = g1 + vyo * DT;

    float* o = out + (size_t)b * 6;     // scalar stores only
    o[0] = sx; o[1] = sy;
    o[2] = vxo; o[3] = vyo;
    o[4] = ax;  o[5] = ay;
}

extern "C" void kernel_launch(void* const* d_in, const int* in_sizes, int n_in,
                              void* d_out, int out_size)
{
    const float* ego    = (const float*)d_in[0];
    const float* nei    = (const float*)d_in[1];
    const float* border = (const float*)d_in[2];
    const float* adp    = (const float*)d_in[3];
    const float* eff    = (const float*)d_in[4];
    const float* an_wi  = (const float*)d_in[5];
    const float* an_bi  = (const float*)d_in[6];
    const float* an_wo  = (const float*)d_in[7];
    const float* an_bo  = (const float*)d_in[8];
    const float* rn_wi  = (const float*)d_in[9];
    const float* rn_bi  = (const float*)d_in[10];
    const float* rn_wo  = (const float*)d_in[11];
    const float* rn_bo  = (const float*)d_in[12];
    const float* rb_wi  = (const float*)d_in[13];
    const float* rb_bi  = (const float*)d_in[14];
    const float* rb_wo  = (const float*)d_in[15];
    const float* rb_bo  = (const float*)d_in[16];
    const float* dl_wi  = (const float*)d_in[17];
    const float* dl_bi  = (const float*)d_in[18];
    const float* dl_wo  = (const float*)d_in[19];
    const float* dl_bo  = (const float*)d_in[20];
    float* out = (float*)d_out;

    int n_batch = in_sizes[0] / (TT * FF);

    sfm_precompute<<<1, 128>>>(ego,
                               an_wi, an_bi, an_wo, an_bo,
                               rn_wi, rn_bi, rn_wo, rn_bo,
                               rb_wi, rb_bi, rb_wo, rb_bo,
                               dl_wi, dl_bi, dl_wo, dl_bo);

    int blocks = (n_batch + 255) / 256;
    sfm_main<<<blocks, 256>>>(ego, nei, border, adp, eff, out, n_batch);
}